// round 4
// baseline (speedup 1.0000x reference)
#include <cuda_runtime.h>
#include <cuda_bf16.h>
#include <cstdint>

// GAT fused kernel, GB300 sm_103a.
// B=8, N=512, T=128, DIN=DOUT=128, H=8, HD=16.
//
// Factorization (exactly equivalent to reference):
//   softmax-effective score[b,t,h,n] = h[b,n,t,:] . wtil_h      (constants cancel)
//     wtil_h[k] = sum_d W1[k, h*16+d] * Wa[16+d]
//   e = mask * exp(score);  w = e * rv,  rv = 1/(adj==0 ? 1e9 : adj)
//   Z_h = sum_n e;  S_h = (sum_n w)/Z_h;  g_h = (sum_n w*h_n)/Z_h
//   agg[h*16+d] = g_h . W1[:, h*16+d] + S_h * b1[h*16+d]
//   out = agg @ W2[:128] + h0 @ M + c,   M = W1 @ W2[128:],  c = b1 @ W2[128:] + b2

#define Bv 8
#define Nv 512
#define Tv 128
#define Dv 128
#define Hv 8
#define CH 32          // rows per chunk
#define NCHUNK 16      // Nv / CH
#define ROWP 132       // padded row pitch (floats): conflict-free smem

// ---------------- scratch (device globals: allowed) ----------------
__device__ float G_scr[Bv * Tv * Hv * Dv];   // 4 MB: normalized g per (b,t,h)
__device__ float S_scr[Bv * Tv * Hv];        // S per (b,t,h)
__device__ float wtil_g[Hv * Dv];            // 8 x 128
__device__ float M_g[Dv * Dv];               // W1 @ W2b
__device__ float c_g[Dv];                    // b1 @ W2b + b2

// ---------------- prep: wtil, M, c ----------------
__global__ void gat_prep(const float* __restrict__ W1, const float* __restrict__ b1,
                         const float* __restrict__ Wa, const float* __restrict__ W2,
                         const float* __restrict__ b2) {
    int m = blockIdx.x;
    int tid = threadIdx.x;  // 128 threads
    if (m < 128) {
        // M[m][k] = sum_j W1[m][j] * W2[128+j][k]
        float acc = 0.f;
        const float* w1r = W1 + m * 128;
        #pragma unroll 8
        for (int j = 0; j < 128; j++)
            acc += w1r[j] * W2[(128 + j) * 128 + tid];
        M_g[m * 128 + tid] = acc;
    } else {
        // wtil[h][k] = sum_d W1[k][h*16+d] * Wa[16+d]
        for (int idx = tid; idx < 1024; idx += 128) {
            int hh = idx >> 7, k = idx & 127;
            float a = 0.f;
            #pragma unroll
            for (int d = 0; d < 16; d++)
                a += W1[k * 128 + hh * 16 + d] * Wa[16 + d];
            wtil_g[idx] = a;
        }
        // c[k] = sum_j b1[j]*W2[128+j][k] + b2[k]
        float acc = b2[tid];
        #pragma unroll 8
        for (int j = 0; j < 128; j++)
            acc += b1[j] * W2[(128 + j) * 128 + tid];
        c_g[tid] = acc;
    }
}

// ---------------- main: stream h, attention stats ----------------
__global__ __launch_bounds__(256) void gat_main(const float* __restrict__ hin,
                                                const float* __restrict__ adj,
                                                const float* __restrict__ mask) {
    __shared__ __align__(16) float hbuf[2][CH * ROWP];   // 33792 B
    __shared__ __align__(16) float wts[Hv * ROWP];       // 4224 B
    __shared__ float ws[CH * 9];                          // w per (row, head)
    __shared__ float mk[2][CH];
    __shared__ float rv[2][CH];
    __shared__ float zred[8][8], wred[8][8];
    __shared__ float invZs[8], unused_pad[8];

    const int bt = blockIdx.x;
    const int b = bt >> 7;
    const int t = bt & 127;
    const int tid = threadIdx.x;

    // stage wtil with pitch 132
    for (int idx = tid; idx < 1024; idx += 256)
        wts[(idx >> 7) * ROWP + (idx & 127)] = wtil_g[idx];

    // ---- async chunk loader ----
    auto issue = [&](int c) {
        const int buf = c & 1;
        const float* base = hin + (((size_t)(b * Nv + c * CH)) * Tv + t) * Dv;
        #pragma unroll
        for (int i = 0; i < 4; i++) {
            int lin = i * 256 + tid;
            int r = lin >> 5;        // row in chunk
            int j = lin & 31;        // float4 within row
            const float* gp = base + (size_t)r * (Tv * Dv) + j * 4;
            unsigned sa = (unsigned)__cvta_generic_to_shared(&hbuf[buf][r * ROWP + j * 4]);
            asm volatile("cp.async.cg.shared.global [%0], [%1], 16;" :: "r"(sa), "l"(gp));
        }
        if (tid < 32) {
            int n = c * CH + tid;
            mk[buf][tid] = mask[(size_t)(b * Nv + n) * Tv + t];
        } else if (tid < 64) {
            int r = tid - 32;
            int n = c * CH + r;
            float a = adj[(size_t)(b * Tv + t) * Nv + n];
            a = (a == 0.f) ? 1e9f : a;
            rv[buf][r] = 1.0f / a;
        }
        asm volatile("cp.async.commit_group;");
    };

    issue(0);

    // phase A identity: thread = (row rA, head hA)
    const int rA = tid >> 3;
    const int hA = tid & 7;
    // phase B identity: warp = 4 heads x 8 col-quads
    const int w2 = tid >> 5;
    const int l  = tid & 31;
    const int hB  = ((w2 & 1) << 2) + (l >> 3);
    const int kcB = ((w2 >> 1) << 3) + (l & 7);

    float4 gacc = make_float4(0.f, 0.f, 0.f, 0.f);
    float zsum = 0.f, wsum = 0.f;

    #pragma unroll 1
    for (int c = 0; c < NCHUNK; c++) {
        if (c + 1 < NCHUNK) {
            issue(c + 1);
            asm volatile("cp.async.wait_group 1;");
        } else {
            asm volatile("cp.async.wait_group 0;");
        }
        __syncthreads();
        const int buf = c & 1;

        // ---- phase A: scores ----
        {
            const float4* hr = (const float4*)&hbuf[buf][rA * ROWP];
            const float4* wr = (const float4*)&wts[hA * ROWP];
            float4 acc = make_float4(0.f, 0.f, 0.f, 0.f);
            #pragma unroll
            for (int j = 0; j < 32; j++) {
                float4 a4 = hr[j];
                float4 b4 = wr[j];
                acc.x += a4.x * b4.x;
                acc.y += a4.y * b4.y;
                acc.z += a4.z * b4.z;
                acc.w += a4.w * b4.w;
            }
            float score = (acc.x + acc.y) + (acc.z + acc.w);
            float e = mk[buf][rA] * __expf(score);
            float w = e * rv[buf][rA];
            ws[rA * 9 + hA] = w;
            zsum += e;
            wsum += w;
        }
        __syncthreads();

        // ---- phase B: weighted accumulation G_h += w * h_n ----
        {
            const float4* hb = (const float4*)&hbuf[buf][0];
            #pragma unroll
            for (int r = 0; r < CH; r++) {
                float wv = ws[r * 9 + hB];
                float4 x = hb[r * 33 + kcB];   // 33 = ROWP/4
                gacc.x += wv * x.x;
                gacc.y += wv * x.y;
                gacc.z += wv * x.z;
                gacc.w += wv * x.w;
            }
        }
        __syncthreads();
    }

    // ---- reduce Z, Sw per head ----
    zsum += __shfl_xor_sync(0xffffffffu, zsum, 8);
    zsum += __shfl_xor_sync(0xffffffffu, zsum, 16);
    wsum += __shfl_xor_sync(0xffffffffu, wsum, 8);
    wsum += __shfl_xor_sync(0xffffffffu, wsum, 16);
    const int warp = tid >> 5, lane = tid & 31;
    if (lane < 8) { zred[warp][lane] = zsum; wred[warp][lane] = wsum; }
    __syncthreads();
    if (tid < 8) {
        float Z = 0.f, W = 0.f;
        #pragma unroll
        for (int i = 0; i < 8; i++) { Z += zred[i][tid]; W += wred[i][tid]; }
        float iZ = 1.0f / Z;
        invZs[tid] = iZ;
        S_scr[bt * 8 + tid] = W * iZ;
    }
    __syncthreads();

    // ---- write normalized g ----
    {
        float iZ = invZs[hB];
        float4 o = make_float4(gacc.x * iZ, gacc.y * iZ, gacc.z * iZ, gacc.w * iZ);
        *(float4*)&G_scr[(size_t)bt * 1024 + hB * 128 + kcB * 4] = o;
    }
}

// ---------------- epilogue ----------------
// block = (b, tile of 16 t), 256 threads. Processes 8 t per pass (2 passes).
#define EPI_SMEM_FLOATS (16384 + 16384 + 8448 + 1024 + 1024 + 128 + 64)
__global__ __launch_bounds__(256) void gat_epi(const float* __restrict__ hin,
                                               const float* __restrict__ W1,
                                               const float* __restrict__ W2,
                                               const float* __restrict__ b1,
                                               float* __restrict__ out) {
    extern __shared__ __align__(16) float sm[];
    float* w1s  = sm;                    // 16384
    float* w2s  = w1s + 16384;           // 16384 (W2 rows 0..127)
    float* gs   = w2s + 16384;           // 8 t * 8 h * pitch132 = 8448
    float* aggs = gs + 8448;             // 8 * 128
    float* h0s  = aggs + 1024;           // 8 * 128
    float* cs   = h0s + 1024;            // 128
    float* Ss   = cs + 128;              // 64

    const int b = blockIdx.x >> 3;
    const int tile = blockIdx.x & 7;
    const int tid = threadIdx.x;

    for (int idx = tid; idx < 16384; idx += 256) {
        w1s[idx] = W1[idx];
        w2s[idx] = W2[idx];   // rows 0..127 of W2 (W2a)
    }
    if (tid < 128) cs[tid] = c_g[tid];

    #pragma unroll 1
    for (int p = 0; p < 2; p++) {
        __syncthreads();
        const int t0 = tile * 16 + p * 8;
        // stage g (pitch 132 per head) and h0 rows and S
        for (int idx = tid; idx < 8192; idx += 256) {
            int t8 = idx >> 10;
            int hh = (idx >> 7) & 7;
            int m = idx & 127;
            gs[t8 * 1056 + hh * 132 + m] =
                G_scr[((size_t)(b * Tv + t0 + t8) * 8 + hh) * 128 + m];
        }
        for (int idx = tid; idx < 1024; idx += 256) {
            int t8 = idx >> 7;
            int m = idx & 127;
            h0s[idx] = hin[((size_t)(b * Nv + 0) * Tv + (t0 + t8)) * Dv + m];
        }
        if (tid < 64) {
            int t8 = tid >> 3, hh = tid & 7;
            Ss[tid] = S_scr[(b * Tv + t0 + t8) * 8 + hh];
        }
        __syncthreads();

        // agg[j] = g_h . W1[:,j] + S_h * b1[j]   (thread: t8 = warp, 4 j's)
        {
            const int t8 = tid >> 5;
            const int jq = tid & 31;
            const int hh = jq >> 2;
            float4 bv = ((const float4*)b1)[jq];
            float S = Ss[t8 * 8 + hh];
            float4 a4 = make_float4(S * bv.x, S * bv.y, S * bv.z, S * bv.w);
            const float* gp = &gs[t8 * 1056 + hh * 132];
            const float4* w1p = (const float4*)w1s;
            #pragma unroll 8
            for (int m = 0; m < 128; m++) {
                float g = gp[m];
                float4 wv = w1p[m * 32 + jq];
                a4.x += g * wv.x; a4.y += g * wv.y;
                a4.z += g * wv.z; a4.w += g * wv.w;
            }
            ((float4*)aggs)[t8 * 32 + jq] = a4;
        }
        __syncthreads();

        // out[k] = agg @ W2a + h0 @ M + c
        {
            const int t8 = tid >> 5;
            const int kq = tid & 31;
            float4 o4 = ((const float4*)cs)[kq];
            const float* ap = &aggs[t8 * 128];
            const float4* w2p = (const float4*)w2s;
            #pragma unroll 8
            for (int j = 0; j < 128; j++) {
                float a = ap[j];
                float4 wv = w2p[j * 32 + kq];
                o4.x += a * wv.x; o4.y += a * wv.y;
                o4.z += a * wv.z; o4.w += a * wv.w;
            }
            const float* hp = &h0s[t8 * 128];
            const float4* Mp = (const float4*)M_g;
            #pragma unroll 8
            for (int m = 0; m < 128; m++) {
                float hv = hp[m];
                float4 wv = Mp[m * 32 + kq];
                o4.x += hv * wv.x; o4.y += hv * wv.y;
                o4.z += hv * wv.z; o4.w += hv * wv.w;
            }
            int t = t0 + t8;
            ((float4*)out)[(b * Tv + t) * 32 + kq] = o4;
        }
    }
}

// ---------------- launch ----------------
extern "C" void kernel_launch(void* const* d_in, const int* in_sizes, int n_in,
                              void* d_out, int out_size) {
    const float* h    = (const float*)d_in[0];
    const float* adj  = (const float*)d_in[1];
    const float* mask = (const float*)d_in[2];
    const float* W1   = (const float*)d_in[3];
    const float* b1   = (const float*)d_in[4];
    const float* Wa   = (const float*)d_in[5];
    // d_in[6] = ba (cancels in softmax; unused)
    const float* W2   = (const float*)d_in[7];
    const float* b2   = (const float*)d_in[8];
    float* out = (float*)d_out;

    cudaFuncSetAttribute(gat_epi, cudaFuncAttributeMaxDynamicSharedMemorySize,
                         EPI_SMEM_FLOATS * (int)sizeof(float));

    gat_prep<<<129, 128>>>(W1, b1, Wa, W2, b2);
    gat_main<<<Bv * Tv, 256>>>(h, adj, mask);
    gat_epi<<<64, 256, EPI_SMEM_FLOATS * sizeof(float)>>>(h, W1, W2, b1, out);
}

// round 5
// speedup vs baseline: 1.0028x; 1.0028x over previous
#include <cuda_runtime.h>
#include <cuda_bf16.h>
#include <cstdint>

// GAT fused kernel, GB300 sm_103a.
// B=8, N=512, T=128, DIN=DOUT=128, H=8, HD=16.
//
// Factorization (exactly equivalent to reference):
//   softmax-effective score[b,t,h,n] = h[b,n,t,:] . wtil_h      (constants cancel)
//     wtil_h[k] = sum_d W1[k, h*16+d] * Wa[16+d]
//   e = mask * exp(score);  w = e * rv,  rv = 1/(adj==0 ? 1e9 : adj)
//   Z_h = sum_n e;  S_h = (sum_n w)/Z_h;  g_h = (sum_n w*h_n)/Z_h
//   agg[h*16+d] = g_h . W1[:, h*16+d] + S_h * b1[h*16+d]
//   out = agg @ W2[:128] + h0 @ M + c,   M = W1 @ W2[128:],  c = b1 @ W2[128:] + b2

#define Bv 8
#define Nv 512
#define Tv 128
#define Dv 128
#define Hv 8
#define CH 32          // rows per chunk
#define NCHUNK 16      // Nv / CH
#define ROWP 132       // padded row pitch (floats): conflict-free smem

// ---------------- scratch (device globals: allowed) ----------------
__device__ float G_scr[Bv * Tv * Hv * Dv];   // 4 MB: normalized g per (b,t,h)
__device__ float S_scr[Bv * Tv * Hv];        // S per (b,t,h)
__device__ float wtil_g[Hv * Dv];            // 8 x 128
__device__ float M_g[Dv * Dv];               // W1 @ W2b
__device__ float c_g[Dv];                    // b1 @ W2b + b2

// ---------------- prep: wtil, M, c ----------------
__global__ void gat_prep(const float* __restrict__ W1, const float* __restrict__ b1,
                         const float* __restrict__ Wa, const float* __restrict__ W2,
                         const float* __restrict__ b2) {
    int m = blockIdx.x;
    int tid = threadIdx.x;  // 128 threads
    if (m < 128) {
        // M[m][k] = sum_j W1[m][j] * W2[128+j][k]
        float acc = 0.f;
        const float* w1r = W1 + m * 128;
        #pragma unroll 8
        for (int j = 0; j < 128; j++)
            acc += w1r[j] * W2[(128 + j) * 128 + tid];
        M_g[m * 128 + tid] = acc;
    } else {
        // wtil[h][k] = sum_d W1[k][h*16+d] * Wa[16+d]
        for (int idx = tid; idx < 1024; idx += 128) {
            int hh = idx >> 7, k = idx & 127;
            float a = 0.f;
            #pragma unroll
            for (int d = 0; d < 16; d++)
                a += W1[k * 128 + hh * 16 + d] * Wa[16 + d];
            wtil_g[idx] = a;
        }
        // c[k] = sum_j b1[j]*W2[128+j][k] + b2[k]
        float acc = b2[tid];
        #pragma unroll 8
        for (int j = 0; j < 128; j++)
            acc += b1[j] * W2[(128 + j) * 128 + tid];
        c_g[tid] = acc;
    }
}

// ---------------- main: stream h, attention stats ----------------
__global__ __launch_bounds__(256) void gat_main(const float* __restrict__ hin,
                                                const float* __restrict__ adj,
                                                const float* __restrict__ mask) {
    __shared__ __align__(16) float hbuf[2][CH * ROWP];   // 33792 B
    __shared__ __align__(16) float wts[Hv * ROWP];       // 4224 B
    __shared__ float ws[CH * 9];                          // w per (row, head)
    __shared__ float mk[2][CH];
    __shared__ float rv[2][CH];
    __shared__ float zred[8][8], wred[8][8];
    __shared__ float invZs[8], unused_pad[8];

    const int bt = blockIdx.x;
    const int b = bt >> 7;
    const int t = bt & 127;
    const int tid = threadIdx.x;

    // stage wtil with pitch 132
    for (int idx = tid; idx < 1024; idx += 256)
        wts[(idx >> 7) * ROWP + (idx & 127)] = wtil_g[idx];

    // ---- async chunk loader ----
    auto issue = [&](int c) {
        const int buf = c & 1;
        const float* base = hin + (((size_t)(b * Nv + c * CH)) * Tv + t) * Dv;
        #pragma unroll
        for (int i = 0; i < 4; i++) {
            int lin = i * 256 + tid;
            int r = lin >> 5;        // row in chunk
            int j = lin & 31;        // float4 within row
            const float* gp = base + (size_t)r * (Tv * Dv) + j * 4;
            unsigned sa = (unsigned)__cvta_generic_to_shared(&hbuf[buf][r * ROWP + j * 4]);
            asm volatile("cp.async.cg.shared.global [%0], [%1], 16;" :: "r"(sa), "l"(gp));
        }
        if (tid < 32) {
            int n = c * CH + tid;
            mk[buf][tid] = mask[(size_t)(b * Nv + n) * Tv + t];
        } else if (tid < 64) {
            int r = tid - 32;
            int n = c * CH + r;
            float a = adj[(size_t)(b * Tv + t) * Nv + n];
            a = (a == 0.f) ? 1e9f : a;
            rv[buf][r] = 1.0f / a;
        }
        asm volatile("cp.async.commit_group;");
    };

    issue(0);

    // phase A identity: thread = (row rA, head hA)
    const int rA = tid >> 3;
    const int hA = tid & 7;
    // phase B identity: warp = 4 heads x 8 col-quads
    const int w2 = tid >> 5;
    const int l  = tid & 31;
    const int hB  = ((w2 & 1) << 2) + (l >> 3);
    const int kcB = ((w2 >> 1) << 3) + (l & 7);

    float4 gacc = make_float4(0.f, 0.f, 0.f, 0.f);
    float zsum = 0.f, wsum = 0.f;

    #pragma unroll 1
    for (int c = 0; c < NCHUNK; c++) {
        if (c + 1 < NCHUNK) {
            issue(c + 1);
            asm volatile("cp.async.wait_group 1;");
        } else {
            asm volatile("cp.async.wait_group 0;");
        }
        __syncthreads();
        const int buf = c & 1;

        // ---- phase A: scores ----
        {
            const float4* hr = (const float4*)&hbuf[buf][rA * ROWP];
            const float4* wr = (const float4*)&wts[hA * ROWP];
            float4 acc = make_float4(0.f, 0.f, 0.f, 0.f);
            #pragma unroll
            for (int j = 0; j < 32; j++) {
                float4 a4 = hr[j];
                float4 b4 = wr[j];
                acc.x += a4.x * b4.x;
                acc.y += a4.y * b4.y;
                acc.z += a4.z * b4.z;
                acc.w += a4.w * b4.w;
            }
            float score = (acc.x + acc.y) + (acc.z + acc.w);
            float e = mk[buf][rA] * __expf(score);
            float w = e * rv[buf][rA];
            ws[rA * 9 + hA] = w;
            zsum += e;
            wsum += w;
        }
        __syncthreads();

        // ---- phase B: weighted accumulation G_h += w * h_n ----
        {
            const float4* hb = (const float4*)&hbuf[buf][0];
            #pragma unroll
            for (int r = 0; r < CH; r++) {
                float wv = ws[r * 9 + hB];
                float4 x = hb[r * 33 + kcB];   // 33 = ROWP/4
                gacc.x += wv * x.x;
                gacc.y += wv * x.y;
                gacc.z += wv * x.z;
                gacc.w += wv * x.w;
            }
        }
        __syncthreads();
    }

    // ---- reduce Z, Sw per head ----
    zsum += __shfl_xor_sync(0xffffffffu, zsum, 8);
    zsum += __shfl_xor_sync(0xffffffffu, zsum, 16);
    wsum += __shfl_xor_sync(0xffffffffu, wsum, 8);
    wsum += __shfl_xor_sync(0xffffffffu, wsum, 16);
    const int warp = tid >> 5, lane = tid & 31;
    if (lane < 8) { zred[warp][lane] = zsum; wred[warp][lane] = wsum; }
    __syncthreads();
    if (tid < 8) {
        float Z = 0.f, W = 0.f;
        #pragma unroll
        for (int i = 0; i < 8; i++) { Z += zred[i][tid]; W += wred[i][tid]; }
        float iZ = 1.0f / Z;
        invZs[tid] = iZ;
        S_scr[bt * 8 + tid] = W * iZ;
    }
    __syncthreads();

    // ---- write normalized g ----
    {
        float iZ = invZs[hB];
        float4 o = make_float4(gacc.x * iZ, gacc.y * iZ, gacc.z * iZ, gacc.w * iZ);
        *(float4*)&G_scr[(size_t)bt * 1024 + hB * 128 + kcB * 4] = o;
    }
}

// ---------------- epilogue ----------------
// block = (b, tile of 16 t), 256 threads. Processes 8 t per pass (2 passes).
#define EPI_SMEM_FLOATS (16384 + 16384 + 8448 + 1024 + 1024 + 128 + 64)
__global__ __launch_bounds__(256) void gat_epi(const float* __restrict__ hin,
                                               const float* __restrict__ W1,
                                               const float* __restrict__ W2,
                                               const float* __restrict__ b1,
                                               float* __restrict__ out) {
    extern __shared__ __align__(16) float sm[];
    float* w1s  = sm;                    // 16384
    float* w2s  = w1s + 16384;           // 16384 (W2 rows 0..127)
    float* gs   = w2s + 16384;           // 8 t * 8 h * pitch132 = 8448
    float* aggs = gs + 8448;             // 8 * 128
    float* h0s  = aggs + 1024;           // 8 * 128
    float* cs   = h0s + 1024;            // 128
    float* Ss   = cs + 128;              // 64

    const int b = blockIdx.x >> 3;
    const int tile = blockIdx.x & 7;
    const int tid = threadIdx.x;

    for (int idx = tid; idx < 16384; idx += 256) {
        w1s[idx] = W1[idx];
        w2s[idx] = W2[idx];   // rows 0..127 of W2 (W2a)
    }
    if (tid < 128) cs[tid] = c_g[tid];

    #pragma unroll 1
    for (int p = 0; p < 2; p++) {
        __syncthreads();
        const int t0 = tile * 16 + p * 8;
        // stage g (pitch 132 per head) and h0 rows and S
        for (int idx = tid; idx < 8192; idx += 256) {
            int t8 = idx >> 10;
            int hh = (idx >> 7) & 7;
            int m = idx & 127;
            gs[t8 * 1056 + hh * 132 + m] =
                G_scr[((size_t)(b * Tv + t0 + t8) * 8 + hh) * 128 + m];
        }
        for (int idx = tid; idx < 1024; idx += 256) {
            int t8 = idx >> 7;
            int m = idx & 127;
            h0s[idx] = hin[((size_t)(b * Nv + 0) * Tv + (t0 + t8)) * Dv + m];
        }
        if (tid < 64) {
            int t8 = tid >> 3, hh = tid & 7;
            Ss[tid] = S_scr[(b * Tv + t0 + t8) * 8 + hh];
        }
        __syncthreads();

        // agg[j] = g_h . W1[:,j] + S_h * b1[j]   (thread: t8 = warp, 4 j's)
        {
            const int t8 = tid >> 5;
            const int jq = tid & 31;
            const int hh = jq >> 2;
            float4 bv = ((const float4*)b1)[jq];
            float S = Ss[t8 * 8 + hh];
            float4 a4 = make_float4(S * bv.x, S * bv.y, S * bv.z, S * bv.w);
            const float* gp = &gs[t8 * 1056 + hh * 132];
            const float4* w1p = (const float4*)w1s;
            #pragma unroll 8
            for (int m = 0; m < 128; m++) {
                float g = gp[m];
                float4 wv = w1p[m * 32 + jq];
                a4.x += g * wv.x; a4.y += g * wv.y;
                a4.z += g * wv.z; a4.w += g * wv.w;
            }
            ((float4*)aggs)[t8 * 32 + jq] = a4;
        }
        __syncthreads();

        // out[k] = agg @ W2a + h0 @ M + c
        {
            const int t8 = tid >> 5;
            const int kq = tid & 31;
            float4 o4 = ((const float4*)cs)[kq];
            const float* ap = &aggs[t8 * 128];
            const float4* w2p = (const float4*)w2s;
            #pragma unroll 8
            for (int j = 0; j < 128; j++) {
                float a = ap[j];
                float4 wv = w2p[j * 32 + kq];
                o4.x += a * wv.x; o4.y += a * wv.y;
                o4.z += a * wv.z; o4.w += a * wv.w;
            }
            const float* hp = &h0s[t8 * 128];
            const float4* Mp = (const float4*)M_g;
            #pragma unroll 8
            for (int m = 0; m < 128; m++) {
                float hv = hp[m];
                float4 wv = Mp[m * 32 + kq];
                o4.x += hv * wv.x; o4.y += hv * wv.y;
                o4.z += hv * wv.z; o4.w += hv * wv.w;
            }
            int t = t0 + t8;
            ((float4*)out)[(b * Tv + t) * 32 + kq] = o4;
        }
    }
}

// ---------------- launch ----------------
extern "C" void kernel_launch(void* const* d_in, const int* in_sizes, int n_in,
                              void* d_out, int out_size) {
    const float* h    = (const float*)d_in[0];
    const float* adj  = (const float*)d_in[1];
    const float* mask = (const float*)d_in[2];
    const float* W1   = (const float*)d_in[3];
    const float* b1   = (const float*)d_in[4];
    const float* Wa   = (const float*)d_in[5];
    // d_in[6] = ba (cancels in softmax; unused)
    const float* W2   = (const float*)d_in[7];
    const float* b2   = (const float*)d_in[8];
    float* out = (float*)d_out;

    cudaFuncSetAttribute(gat_epi, cudaFuncAttributeMaxDynamicSharedMemorySize,
                         EPI_SMEM_FLOATS * (int)sizeof(float));

    gat_prep<<<129, 128>>>(W1, b1, Wa, W2, b2);
    gat_main<<<Bv * Tv, 256>>>(h, adj, mask);
    gat_epi<<<64, 256, EPI_SMEM_FLOATS * sizeof(float)>>>(h, W1, W2, b1, out);
}